// round 15
// baseline (speedup 1.0000x reference)
#include <cuda_runtime.h>

#define NVEH 4096
#define NT 256
#define PAST 25
#define LEADLEN (NT + PAST - 1)   // 280
#define NPAIR (NVEH / 2)          // 2048
#define WARPS_PER_CTA 14
#define NCTA ((NPAIR + WARPS_PER_CTA - 1) / WARPS_PER_CTA)   // 147
#define NTHREADS (WARPS_PER_CTA * 32)                         // 448

typedef unsigned long long ull;

// ---- shared memory layout (float offsets) ----
#define W1_OFF    0        // 288  : conv1_w [3][3][32]
#define B1_OFF    288      // 32
#define B2P_OFF   320      // 64   : float2 {b2[c], b2[c+32]}
#define W2X_OFF   384      // 4096 : float4 [ci*32+c] = {w0[c], w0[c+32], w1[c], w1[c+32]}
#define W2K2_OFF  4480     // 2048 : float4 [cp*32+c] = {k2[2cp][c], k2[2cp][c+32], k2[2cp+1][c], k2[2cp+1][c+32]}
#define WD2X_OFF  6528     // 3840 : ull2 [(q*6+jj)*32+c] = {pair_i, pair_{i+32}}
#define BD2_OFF   10368    // 10
#define WD1_OFF   10378    // 10
#define BD1_OFF   10388    // 1 (+3 pad)
#define XBUF_OFF  10392    // 14 sets * 27 pos * 8 floats = 3024
#define PQ_OFF    13416    // pool1 circular: 14 sets * 2 parities * 13 slots * 32 * float2
#define SC_OFF    (PQ_OFF + 14 * 2 * 13 * 32 * 2)   // 36712 : conv2 odd state, 14 sets * 2 arr * 11 slots * 32 ull
#define SMEM_FLOATS (SC_OFF + 14 * 2 * 11 * 32 * 2) // 56424 floats = 225696 B

__device__ __forceinline__ ull ffma2(ull a, ull b, ull c) {
    ull d;
    asm("fma.rn.f32x2 %0, %1, %2, %3;" : "=l"(d) : "l"(a), "l"(b), "l"(c));
    return d;
}
__device__ __forceinline__ ull addf32x2(ull a, ull b) {
    ull d;
    asm("add.rn.f32x2 %0, %1, %2;" : "=l"(d) : "l"(a), "l"(b));
    return d;
}
__device__ __forceinline__ void unpk(ull v, float& lo, float& hi) {
    asm("mov.b64 {%0, %1}, %2;" : "=f"(lo), "=f"(hi) : "l"(v));
}
__device__ __forceinline__ ull pkdup(float x) {
    ull d;
    asm("mov.b64 %0, {%1, %1};" : "=l"(d) : "f"(x));
    return d;
}
__device__ __forceinline__ int wrap13(int x) { return x >= 13 ? x - 13 : x; }
__device__ __forceinline__ int wrap11(int x) { return x >= 11 ? x - 11 : x; }

__global__ void __launch_bounds__(NTHREADS, 1)
rnncf_kernel(const float* __restrict__ lead, const float* __restrict__ cur,
             const float* __restrict__ w1g, const float* __restrict__ b1g,
             const float* __restrict__ w2g, const float* __restrict__ b2g,
             const float* __restrict__ wd2g, const float* __restrict__ bd2g,
             const float* __restrict__ wd1g, const float* __restrict__ bd1g,
             float* __restrict__ out)
{
    extern __shared__ float sm[];
    const int tid = threadIdx.x;

    // ---------- cooperative weight staging ----------
    for (int i = tid; i < 288; i += NTHREADS) sm[W1_OFF + i] = w1g[i];
    for (int i = tid; i < 32;  i += NTHREADS) sm[B1_OFF + i] = b1g[i];
    {
        float2* b2p_s = (float2*)(sm + B2P_OFF);
        for (int i = tid; i < 32; i += NTHREADS)
            b2p_s[i] = make_float2(b2g[i], b2g[i + 32]);
        float4* w2x_s = (float4*)(sm + W2X_OFF);
        for (int i = tid; i < 1024; i += NTHREADS) {
            int ci = i >> 5, c = i & 31;
            w2x_s[i] = make_float4(w2g[ci * 64 + c],        w2g[ci * 64 + c + 32],
                                   w2g[(32 + ci) * 64 + c], w2g[(32 + ci) * 64 + c + 32]);
        }
        float4* w2k2_s = (float4*)(sm + W2K2_OFF);
        for (int i = tid; i < 512; i += NTHREADS) {
            int cp = i >> 5, c = i & 31;
            w2k2_s[i] = make_float4(w2g[(64 + 2 * cp) * 64 + c],     w2g[(64 + 2 * cp) * 64 + c + 32],
                                    w2g[(64 + 2 * cp + 1) * 64 + c], w2g[(64 + 2 * cp + 1) * 64 + c + 32]);
        }
        float4* wdx_s = (float4*)(sm + WD2X_OFF);
        for (int i = tid; i < 960; i += NTHREADS) {
            int q = i / 192, r = i - q * 192;
            int jj = r >> 5, c = r & 31;
            int ii = jj * 64 + c;
            wdx_s[i] = make_float4(wd2g[ii * 10 + 2 * q],        wd2g[ii * 10 + 2 * q + 1],
                                   wd2g[(ii + 32) * 10 + 2 * q], wd2g[(ii + 32) * 10 + 2 * q + 1]);
        }
    }
    for (int i = tid; i < 10; i += NTHREADS) sm[BD2_OFF + i] = bd2g[i];
    for (int i = tid; i < 10; i += NTHREADS) sm[WD1_OFF + i] = wd1g[i];
    if (tid == 0) sm[BD1_OFF] = bd1g[0];
    // zero xbuf: border slots (0 and 26) must stay zero (pad columns)
    for (int i = tid; i < 14 * 27 * 8; i += NTHREADS) sm[XBUF_OFF + i] = 0.0f;
    __syncthreads();

    const int wid = tid >> 5, lane = tid & 31;
    const int pairIdx = blockIdx.x * WARPS_PER_CTA + wid;
    if (pairIdx >= NPAIR) return;

    // one vehicle-pair set per warp (set index = wid)
    float* xbuf = sm + XBUF_OFF + wid * (27 * 8);
    float2* pqE = (float2*)(sm + PQ_OFF) + (wid * 2 + 0) * (13 * 32);
    float2* pqO = (float2*)(sm + PQ_OFF) + (wid * 2 + 1) * (13 * 32);
    const ulonglong2* qE = (const ulonglong2*)pqE;
    const ulonglong2* qO = (const ulonglong2*)pqO;
    ull* ScLo = (ull*)(sm + SC_OFF) + wid * (2 * 11 * 32);
    ull* ScHi = ScLo + 11 * 32;
    const float4* w2xf   = (const float4*)(sm + W2X_OFF);
    const float4* w2k2f4 = (const float4*)(sm + W2K2_OFF);
    const ulonglong2* wdx = (const ulonglong2*)(sm + WD2X_OFF);

    const float2* lead2base = (const float2*)lead + (size_t)(2 * pairIdx) * LEADLEN;
    float2*       out2base  = (float2*)out + (size_t)(2 * pairIdx) * NT;

    // hoisted packed constants
    ull w1d[9];
    #pragma unroll
    for (int i = 0; i < 9; ++i) w1d[i] = pkdup(sm[W1_OFF + i * 32 + lane]);
    const ull b1d = pkdup(sm[B1_OFF + lane]);
    ull b2lo, b2hi;
    {
        float2 b2v = ((const float2*)(sm + B2P_OFF))[lane];
        b2lo = pkdup(b2v.x);
        b2hi = pkdup(b2v.y);
    }

    // ---------- initial window: lane i (<25) holds column i, packed {A,B} ----------
    float2 xw0 = make_float2(0.f, 0.f), xw1 = make_float2(0.f, 0.f), xw2 = make_float2(0.f, 0.f);
    float p24v[2], s24v[2];
    {
        float tp[2] = {0.f, 0.f}, ts[2] = {0.f, 0.f};
        if (lane < PAST) {
            const float2* cur2base = (const float2*)cur + (size_t)(2 * pairIdx) * PAST;
            float2 csA = cur2base[lane],            ldA = lead2base[lane];
            float2 csB = cur2base[PAST + lane],     ldB = lead2base[LEADLEN + lane];
            xw0 = make_float2((ldA.x - csA.x) * (1.0f / 200.0f), (ldB.x - csB.x) * (1.0f / 200.0f));
            xw1 = make_float2(csA.y * (1.0f / 40.0f), csB.y * (1.0f / 40.0f));
            xw2 = make_float2(ldA.y * (1.0f / 40.0f), ldB.y * (1.0f / 40.0f));
            tp[0] = csA.x; ts[0] = csA.y; tp[1] = csB.x; ts[1] = csB.y;
        }
        #pragma unroll
        for (int i = 0; i < 2; ++i) {
            p24v[i] = __shfl_sync(0xffffffffu, tp[i], 24);
            s24v[i] = __shfl_sync(0xffffffffu, ts[i], 24);
        }
    }
    float2 ldnv[2];

    // circular bases + conv2 pool1 read offsets
    int bPe = 0, bPo = 0, bS = 0;
    int so7[7];

    // ---------- helpers ----------
    auto publish_full = [&]() {
        if (lane < PAST) {
            *(float4*)(xbuf + (lane + 1) * 8)     = make_float4(xw0.x, xw0.y, xw1.x, xw1.y);
            *(float2*)(xbuf + (lane + 1) * 8 + 4) = xw2;
        }
        __syncwarp();
    };
    auto publish_part = [&]() {   // only cols needed by fresh conv positions
        bool w = (lane < 3) || (lane >= 21 && lane < 25);
        if (w) {
            *(float4*)(xbuf + (lane + 1) * 8)     = make_float4(xw0.x, xw0.y, xw1.x, xw1.y);
            *(float2*)(xbuf + (lane + 1) * 8 + 4) = xw2;
        }
        __syncwarp();
    };

    auto c1p3 = [&](ulonglong2 a01, ull a2, ulonglong2 b01, ull b2_, ulonglong2 c01, ull c2) -> ull {
        ull h = b1d;
        h = ffma2(a01.x, w1d[0], h); h = ffma2(a01.y, w1d[1], h); h = ffma2(a2,  w1d[2], h);
        h = ffma2(b01.x, w1d[3], h); h = ffma2(b01.y, w1d[4], h); h = ffma2(b2_, w1d[5], h);
        h = ffma2(c01.x, w1d[6], h); h = ffma2(c01.y, w1d[7], h); h = ffma2(c2,  w1d[8], h);
        return h;
    };
    auto poolpair = [&](ull h0, ull h1) -> float2 {
        float f0A, f0B, f1A, f1B;
        unpk(h0, f0A, f0B); unpk(h1, f1A, f1B);
        return make_float2(fmaxf(fmaxf(f0A, 0.f), fmaxf(f1A, 0.f)),
                           fmaxf(fmaxf(f0B, 0.f), fmaxf(f1B, 0.f)));
    };
    auto poolone = [&](ull h0) -> float2 {
        float f0A, f0B;
        unpk(h0, f0A, f0B);
        return make_float2(fmaxf(f0A, 0.f), fmaxf(f0B, 0.f));
    };

    auto conv1_full = [&](float2* pd) {   // seeds: all 13 slots at base 0
        ulonglong2 a01 = *(const ulonglong2*)(xbuf);
        ull        a2  = *(const ull*)(xbuf + 4);
        ulonglong2 b01 = *(const ulonglong2*)(xbuf + 8);
        ull        b2_ = *(const ull*)(xbuf + 12);
        #pragma unroll
        for (int m = 0; m < 12; ++m) {
            ulonglong2 c01 = *(const ulonglong2*)(xbuf + (2 * m + 2) * 8);
            ull        c2  = *(const ull*)(xbuf + (2 * m + 2) * 8 + 4);
            ulonglong2 d01 = *(const ulonglong2*)(xbuf + (2 * m + 3) * 8);
            ull        d2  = *(const ull*)(xbuf + (2 * m + 3) * 8 + 4);
            ull h0 = c1p3(a01, a2, b01, b2_, c01, c2);
            ull h1 = c1p3(b01, b2_, c01, c2, d01, d2);
            pd[m * 32 + lane] = poolpair(h0, h1);
            a01 = c01; a2 = c2; b01 = d01; b2_ = d2;
        }
        ulonglong2 c01 = *(const ulonglong2*)(xbuf + 26 * 8);
        ull        c2  = *(const ull*)(xbuf + 26 * 8 + 4);
        pd[12 * 32 + lane] = poolone(c1p3(a01, a2, b01, b2_, c01, c2));
    };

    // steady-state conv1: only fresh conv positions {0,1,22,23,24}
    auto conv1_fresh = [&](float2* pd, int w0i, int w11i, int w12i) {
        ulonglong2 u1 = *(const ulonglong2*)(xbuf + 1 * 8);  ull v1 = *(const ull*)(xbuf + 1 * 8 + 4);   // col0
        ulonglong2 u2 = *(const ulonglong2*)(xbuf + 2 * 8);  ull v2 = *(const ull*)(xbuf + 2 * 8 + 4);   // col1
        ulonglong2 u3 = *(const ulonglong2*)(xbuf + 3 * 8);  ull v3 = *(const ull*)(xbuf + 3 * 8 + 4);   // col2
        ull h0 = b1d;   // conv pos 0: pad, c0, c1
        h0 = ffma2(u1.x, w1d[3], h0); h0 = ffma2(u1.y, w1d[4], h0); h0 = ffma2(v1, w1d[5], h0);
        h0 = ffma2(u2.x, w1d[6], h0); h0 = ffma2(u2.y, w1d[7], h0); h0 = ffma2(v2, w1d[8], h0);
        ull h1 = c1p3(u1, v1, u2, v2, u3, v3);   // conv pos 1
        pd[w0i * 32 + lane] = poolpair(h0, h1);

        ulonglong2 u22 = *(const ulonglong2*)(xbuf + 22 * 8); ull v22 = *(const ull*)(xbuf + 22 * 8 + 4); // col21
        ulonglong2 u23 = *(const ulonglong2*)(xbuf + 23 * 8); ull v23 = *(const ull*)(xbuf + 23 * 8 + 4); // col22
        ulonglong2 u24 = *(const ulonglong2*)(xbuf + 24 * 8); ull v24 = *(const ull*)(xbuf + 24 * 8 + 4); // col23
        ulonglong2 u25 = *(const ulonglong2*)(xbuf + 25 * 8); ull v25 = *(const ull*)(xbuf + 25 * 8 + 4); // col24
        ull g0 = c1p3(u22, v22, u23, v23, u24, v24);   // conv 22
        ull g1 = c1p3(u23, v23, u24, v24, u25, v25);   // conv 23
        ull g2 = b1d;   // conv 24: c23, c24, pad
        g2 = ffma2(u24.x, w1d[0], g2); g2 = ffma2(u24.y, w1d[1], g2); g2 = ffma2(v24, w1d[2], g2);
        g2 = ffma2(u25.x, w1d[3], g2); g2 = ffma2(u25.y, w1d[4], g2); g2 = ffma2(v25, w1d[5], g2);
        pd[w11i * 32 + lane] = poolpair(g0, g1);
        pd[w12i * 32 + lane] = poolone(g2);
    };

    // seeds: all 11 conv2 positions (buffer at base 0)
    auto conv2_full = [&](const ulonglong2* q, ull* Lo, ull* Hi) {
        #pragma unroll
        for (int j = 0; j < 11; ++j) { Lo[j] = b2lo; Hi[j] = b2hi; }
        #pragma unroll 1
        for (int cp = 0; cp < 16; ++cp) {
            float4 wa0 = w2xf[(2 * cp)     * 32 + lane];
            float4 wa1 = w2xf[(2 * cp + 1) * 32 + lane];
            float4 kk  = w2k2f4[cp * 32 + lane];
            ull d00 = pkdup(wa0.x), d01 = pkdup(wa0.y), d10 = pkdup(wa0.z), d11 = pkdup(wa0.w);
            ull e00 = pkdup(wa1.x), e01 = pkdup(wa1.y), e10 = pkdup(wa1.z), e11 = pkdup(wa1.w);
            ull d20 = pkdup(kk.x),  d21 = pkdup(kk.y),  e20 = pkdup(kk.z),  e21 = pkdup(kk.w);
            #pragma unroll
            for (int m = 0; m < 13; ++m) {
                ulonglong2 qp = q[m * 16 + cp];
                if (m <= 10) {
                    Lo[m] = ffma2(qp.x, d00, Lo[m]); Lo[m] = ffma2(qp.y, e00, Lo[m]);
                    Hi[m] = ffma2(qp.x, d01, Hi[m]); Hi[m] = ffma2(qp.y, e01, Hi[m]);
                }
                if (m >= 1 && m <= 11) {
                    Lo[m-1] = ffma2(qp.x, d10, Lo[m-1]); Lo[m-1] = ffma2(qp.y, e10, Lo[m-1]);
                    Hi[m-1] = ffma2(qp.x, d11, Hi[m-1]); Hi[m-1] = ffma2(qp.y, e11, Hi[m-1]);
                }
                if (m >= 2) {
                    Lo[m-2] = ffma2(qp.x, d20, Lo[m-2]); Lo[m-2] = ffma2(qp.y, e20, Lo[m-2]);
                    Hi[m-2] = ffma2(qp.x, d21, Hi[m-2]); Hi[m-2] = ffma2(qp.y, e21, Hi[m-2]);
                }
            }
        }
    };

    // incremental: fresh conv2 positions {0,9,10}, reads via hoisted so7
    auto conv2_inc = [&](const ulonglong2* q, ull (&nlo)[3], ull (&nhi)[3]) {
        nlo[0] = nlo[1] = nlo[2] = b2lo;
        nhi[0] = nhi[1] = nhi[2] = b2hi;
        #pragma unroll 4
        for (int cp = 0; cp < 16; ++cp) {
            float4 wa0 = w2xf[(2 * cp)     * 32 + lane];
            float4 wa1 = w2xf[(2 * cp + 1) * 32 + lane];
            float4 kk  = w2k2f4[cp * 32 + lane];
            ull d00 = pkdup(wa0.x), d01 = pkdup(wa0.y), d10 = pkdup(wa0.z), d11 = pkdup(wa0.w);
            ull e00 = pkdup(wa1.x), e01 = pkdup(wa1.y), e10 = pkdup(wa1.z), e11 = pkdup(wa1.w);
            ull d20 = pkdup(kk.x),  d21 = pkdup(kk.y),  e20 = pkdup(kk.z),  e21 = pkdup(kk.w);

            ulonglong2 q0 = q[so7[0] + cp], q1 = q[so7[1] + cp], q2 = q[so7[2] + cp];
            nlo[0] = ffma2(q0.x, d00, nlo[0]); nlo[0] = ffma2(q0.y, e00, nlo[0]);
            nhi[0] = ffma2(q0.x, d01, nhi[0]); nhi[0] = ffma2(q0.y, e01, nhi[0]);
            nlo[0] = ffma2(q1.x, d10, nlo[0]); nlo[0] = ffma2(q1.y, e10, nlo[0]);
            nhi[0] = ffma2(q1.x, d11, nhi[0]); nhi[0] = ffma2(q1.y, e11, nhi[0]);
            nlo[0] = ffma2(q2.x, d20, nlo[0]); nlo[0] = ffma2(q2.y, e20, nlo[0]);
            nhi[0] = ffma2(q2.x, d21, nhi[0]); nhi[0] = ffma2(q2.y, e21, nhi[0]);

            ulonglong2 q9  = q[so7[3] + cp], q10 = q[so7[4] + cp];
            ulonglong2 q11 = q[so7[5] + cp], q12 = q[so7[6] + cp];
            nlo[1] = ffma2(q9.x,  d00, nlo[1]); nlo[1] = ffma2(q9.y,  e00, nlo[1]);
            nhi[1] = ffma2(q9.x,  d01, nhi[1]); nhi[1] = ffma2(q9.y,  e01, nhi[1]);
            nlo[1] = ffma2(q10.x, d10, nlo[1]); nlo[1] = ffma2(q10.y, e10, nlo[1]);
            nhi[1] = ffma2(q10.x, d11, nhi[1]); nhi[1] = ffma2(q10.y, e11, nhi[1]);
            nlo[1] = ffma2(q11.x, d20, nlo[1]); nlo[1] = ffma2(q11.y, e20, nlo[1]);
            nhi[1] = ffma2(q11.x, d21, nhi[1]); nhi[1] = ffma2(q11.y, e21, nhi[1]);

            nlo[2] = ffma2(q10.x, d00, nlo[2]); nlo[2] = ffma2(q10.y, e00, nlo[2]);
            nhi[2] = ffma2(q10.x, d01, nhi[2]); nhi[2] = ffma2(q10.y, e01, nhi[2]);
            nlo[2] = ffma2(q11.x, d10, nlo[2]); nlo[2] = ffma2(q11.y, e10, nlo[2]);
            nhi[2] = ffma2(q11.x, d11, nhi[2]); nhi[2] = ffma2(q11.y, e11, nhi[2]);
            nlo[2] = ffma2(q12.x, d20, nlo[2]); nlo[2] = ffma2(q12.y, e20, nlo[2]);
            nhi[2] = ffma2(q12.x, d21, nhi[2]); nhi[2] = ffma2(q12.y, e21, nhi[2]);
        }
    };

    // tail: pool2 + dense2 + 2-way parity reduce + dense1 + recurrence + window shift
    auto tail2 = [&](auto&& gLo, auto&& gHi, int t) {
        ull sA[5] = {0,0,0,0,0}, sB[5] = {0,0,0,0,0};
        #pragma unroll
        for (int jj = 0; jj < 6; ++jj) {
            ull fapA, fbpA, fapB, fbpB;
            float aA, aB, bA, bB;
            if (jj < 5) {
                unpk(gLo(2 * jj), aA, aB); unpk(gLo(2 * jj + 1), bA, bB);
                fapA = pkdup(fmaxf(fmaxf(aA, 0.f), fmaxf(bA, 0.f)));
                fapB = pkdup(fmaxf(fmaxf(aB, 0.f), fmaxf(bB, 0.f)));
                unpk(gHi(2 * jj), aA, aB); unpk(gHi(2 * jj + 1), bA, bB);
                fbpA = pkdup(fmaxf(fmaxf(aA, 0.f), fmaxf(bA, 0.f)));
                fbpB = pkdup(fmaxf(fmaxf(aB, 0.f), fmaxf(bB, 0.f)));
            } else {
                unpk(gLo(10), aA, aB);
                fapA = pkdup(fmaxf(aA, 0.f)); fapB = pkdup(fmaxf(aB, 0.f));
                unpk(gHi(10), aA, aB);
                fbpA = pkdup(fmaxf(aA, 0.f)); fbpB = pkdup(fmaxf(aB, 0.f));
            }
            #pragma unroll
            for (int q = 0; q < 5; ++q) {
                ulonglong2 w = wdx[(q * 6 + jj) * 32 + lane];
                sA[q] = ffma2(fapA, w.x, sA[q]); sA[q] = ffma2(fbpA, w.y, sA[q]);
                sB[q] = ffma2(fapB, w.x, sB[q]); sB[q] = ffma2(fbpB, w.y, sB[q]);
            }
        }
        // parity merge: even lanes vehicle A, odd lanes vehicle B
        const bool bit0 = (lane & 1);
        ull s5[5];
        #pragma unroll
        for (int q = 0; q < 5; ++q) {
            ull z = bit0 ? sB[q] : sA[q];
            ull x = bit0 ? sA[q] : sB[q];
            s5[q] = addf32x2(z, __shfl_xor_sync(0xffffffffu, x, 1));
        }
        #pragma unroll
        for (int off = 2; off <= 16; off <<= 1) {
            #pragma unroll
            for (int q = 0; q < 5; ++q)
                s5[q] = addf32x2(s5[q], __shfl_xor_sync(0xffffffffu, s5[q], off));
        }
        float d[10];
        #pragma unroll
        for (int q = 0; q < 5; ++q) unpk(s5[q], d[2 * q], d[2 * q + 1]);
        float y = sm[BD1_OFF];
        #pragma unroll
        for (int o = 0; o < 10; ++o)
            y = fmaf(fmaxf(d[o] + sm[BD2_OFF + o], 0.0f), sm[WD1_OFF + o], y);
        float accv = fmaf(10.0f, y, -6.0f);
        float av[2];
        av[0] = __shfl_sync(0xffffffffu, accv, 0);
        av[1] = __shfl_sync(0xffffffffu, accv, 1);

        float pp[2], ps[2];
        #pragma unroll
        for (int i = 0; i < 2; ++i) {
            pp[i] = fmaf(0.1f, s24v[i], p24v[i]);
            ps[i] = fmaf(0.1f, av[i],   s24v[i]);
            p24v[i] = pp[i]; s24v[i] = ps[i];
        }
        if (lane < 2) out2base[lane * NT + t] = make_float2(pp[lane], ps[lane]);

        xw0.x = __shfl_down_sync(0xffffffffu, xw0.x, 1);
        xw0.y = __shfl_down_sync(0xffffffffu, xw0.y, 1);
        xw1.x = __shfl_down_sync(0xffffffffu, xw1.x, 1);
        xw1.y = __shfl_down_sync(0xffffffffu, xw1.y, 1);
        xw2.x = __shfl_down_sync(0xffffffffu, xw2.x, 1);
        xw2.y = __shfl_down_sync(0xffffffffu, xw2.y, 1);
        if (lane == 24) {
            xw0 = make_float2((ldnv[0].x - pp[0]) * (1.0f / 200.0f),
                              (ldnv[1].x - pp[1]) * (1.0f / 200.0f));
            xw1 = make_float2(ps[0] * (1.0f / 40.0f), ps[1] * (1.0f / 40.0f));
            xw2 = make_float2(ldnv[0].y * (1.0f / 40.0f), ldnv[1].y * (1.0f / 40.0f));
        }
    };

    // ---------- seed steps (full compute) ----------
    ull Rlo[11], Rhi[11];   // even-parity conv2 state (registers)
    if (lane == 24) {
        ldnv[0] = lead2base[0 + PAST];
        ldnv[1] = lead2base[LEADLEN + 0 + PAST];
    }
    publish_full();
    conv1_full(pqE);
    __syncwarp();
    conv2_full(qE, Rlo, Rhi);
    tail2([&](int j){ return Rlo[j]; }, [&](int j){ return Rhi[j]; }, 0);

    {
        if (lane == 24) {
            ldnv[0] = lead2base[1 + PAST];
            ldnv[1] = lead2base[LEADLEN + 1 + PAST];
        }
        publish_full();
        conv1_full(pqO);
        __syncwarp();
        ull Tlo[11], Thi[11];
        conv2_full(qO, Tlo, Thi);
        tail2([&](int j){ return Tlo[j]; }, [&](int j){ return Thi[j]; }, 1);
        #pragma unroll
        for (int j = 0; j < 11; ++j) {
            ScLo[j * 32 + lane] = Tlo[j];
            ScHi[j * 32 + lane] = Thi[j];
        }
    }

    // ---------- main incremental loop ----------
    #pragma unroll 1
    for (int t = 2; t < NT; t += 2) {
        // ===== even step t : register conv2 state, pool1-even circular =====
        if (lane == 24) {
            ldnv[0] = lead2base[t + PAST];
            ldnv[1] = lead2base[LEADLEN + t + PAST];
        }
        bPe = wrap13(bPe + 1);
        {
            int w0i = bPe, w11i = wrap13(bPe + 11), w12i = wrap13(bPe + 12);
            publish_part();
            conv1_fresh(pqE, w0i, w11i, w12i);
            __syncwarp();
            so7[0] = bPe * 16;
            so7[1] = wrap13(bPe + 1) * 16;
            so7[2] = wrap13(bPe + 2) * 16;
            so7[3] = wrap13(bPe + 9) * 16;
            so7[4] = wrap13(bPe + 10) * 16;
            so7[5] = w11i * 16;
            so7[6] = w12i * 16;
        }
        {
            ull nlo[3], nhi[3];
            conv2_inc(qE, nlo, nhi);
            Rlo[0] = nlo[0]; Rhi[0] = nhi[0];
            #pragma unroll
            for (int j = 1; j <= 8; ++j) { Rlo[j] = Rlo[j + 1]; Rhi[j] = Rhi[j + 1]; }
            Rlo[9] = nlo[1]; Rlo[10] = nlo[2];
            Rhi[9] = nhi[1]; Rhi[10] = nhi[2];
        }
        tail2([&](int j){ return Rlo[j]; }, [&](int j){ return Rhi[j]; }, t);

        // ===== odd step t+1 : circular smem conv2 state, pool1-odd circular =====
        if ((t + 1) < NT - 1) {
            if (lane == 24) {
                ldnv[0] = lead2base[t + 1 + PAST];
                ldnv[1] = lead2base[LEADLEN + t + 1 + PAST];
            }
        } else {
            ldnv[0] = make_float2(0.f, 0.f);
            ldnv[1] = make_float2(0.f, 0.f);
        }
        bPo = wrap13(bPo + 1);
        {
            int w0i = bPo, w11i = wrap13(bPo + 11), w12i = wrap13(bPo + 12);
            publish_part();
            conv1_fresh(pqO, w0i, w11i, w12i);
            __syncwarp();
            so7[0] = bPo * 16;
            so7[1] = wrap13(bPo + 1) * 16;
            so7[2] = wrap13(bPo + 2) * 16;
            so7[3] = wrap13(bPo + 9) * 16;
            so7[4] = wrap13(bPo + 10) * 16;
            so7[5] = w11i * 16;
            so7[6] = w12i * 16;
        }
        {
            ull mlo[3], mhi[3];
            conv2_inc(qO, mlo, mhi);
            bS = wrap11(bS + 1);
            // fresh {0,9,10} forwarded from registers; 1..8 from circular smem
            tail2(
              [&](int j){ return j == 0 ? mlo[0] : (j == 9 ? mlo[1] : (j == 10 ? mlo[2]
                               : ScLo[wrap11(bS + j) * 32 + lane])); },
              [&](int j){ return j == 0 ? mhi[0] : (j == 9 ? mhi[1] : (j == 10 ? mhi[2]
                               : ScHi[wrap11(bS + j) * 32 + lane])); },
              t + 1);
            // deferred state writes (first needed at t+3; slots disjoint from reads)
            int i0 = bS * 32 + lane;
            int i9 = wrap11(bS + 9) * 32 + lane;
            int iX = wrap11(bS + 10) * 32 + lane;
            ScLo[i0] = mlo[0]; ScLo[i9] = mlo[1]; ScLo[iX] = mlo[2];
            ScHi[i0] = mhi[0]; ScHi[i9] = mhi[1]; ScHi[iX] = mhi[2];
        }
    }
}

extern "C" void kernel_launch(void* const* d_in, const int* in_sizes, int n_in,
                              void* d_out, int out_size)
{
    const float* lead = (const float*)d_in[0];   // (4096, 280, 2)
    const float* cur  = (const float*)d_in[1];   // (4096, 25, 2)
    // d_in[2] = mask (unused by the reference computation)
    const float* w1  = (const float*)d_in[3];
    const float* b1  = (const float*)d_in[4];
    const float* w2  = (const float*)d_in[5];
    const float* b2  = (const float*)d_in[6];
    const float* wd2 = (const float*)d_in[7];
    const float* bd2 = (const float*)d_in[8];
    const float* wd1 = (const float*)d_in[9];
    const float* bd1 = (const float*)d_in[10];
    float* out = (float*)d_out;                   // (4096, 256, 2)

    (void)in_sizes; (void)n_in; (void)out_size;

    size_t smem_bytes = (size_t)SMEM_FLOATS * sizeof(float);   // 225696 B
    cudaFuncSetAttribute(rnncf_kernel,
                         cudaFuncAttributeMaxDynamicSharedMemorySize,
                         (int)smem_bytes);
    rnncf_kernel<<<NCTA, NTHREADS, smem_bytes>>>(
        lead, cur, w1, b1, w2, b2, wd2, bd2, wd1, bd1, out);
}